// round 3
// baseline (speedup 1.0000x reference)
#include <cuda_runtime.h>
#include <cstdint>

#define N_NODES 50000
#define F_DIM   64
#define N_EDGES 800000

// Scratch (static device globals -- no allocation allowed)
__device__ float g_Pa[N_NODES * F_DIM];   // feat @ W1[:64,:] + b1
__device__ float g_Pb[N_NODES * F_DIM];   // feat @ W1[64:,:]
__device__ float g_C[N_NODES];            // per-node accumulated coefficient
__device__ float g_sum;                   // sum of scores
__device__ unsigned int g_cnt;            // count(score < 0.7)
__device__ int g_idx64;                   // 1 if edge_index is int64, 0 if int32

// ---------------------------------------------------------------------------
// Detect index dtype: view buffer as int32 pairs; if all odd words of the
// first 512 entries are zero, it's little-endian int64 (high halves == 0
// since indices < 50000). Otherwise int32.
// ---------------------------------------------------------------------------
__global__ void detect_kernel(const int* __restrict__ ei32) {
    if (threadIdx.x == 0 && blockIdx.x == 0) {
        int is64 = 1;
        for (int i = 0; i < 512; i++) {
            if (ei32[2 * i + 1] != 0) { is64 = 0; break; }
        }
        g_idx64 = is64;
    }
}

// ---------------------------------------------------------------------------
// Zero the accumulators
// ---------------------------------------------------------------------------
__global__ void zero_kernel() {
    int i = blockIdx.x * 256 + threadIdx.x;
    if (i < N_NODES) g_C[i] = 0.0f;
    if (i == 0) { g_sum = 0.0f; g_cnt = 0u; }
}

// ---------------------------------------------------------------------------
// Precompute: Pa[n] = feat[n] @ W1[0:64,:] + b1 ;  Pb[n] = feat[n] @ W1[64:128,:]
// One warp per node; lane j computes outputs j and j+32.
// ---------------------------------------------------------------------------
__global__ __launch_bounds__(128) void precompute_kernel(
    const float* __restrict__ feat,
    const float* __restrict__ W1,
    const float* __restrict__ b1)
{
    __shared__ float W1s[128 * 64];
    __shared__ float b1s[64];
    __shared__ float fs[4][64];

    int tid = threadIdx.x;
    for (int i = tid; i < 128 * 64; i += 128) W1s[i] = W1[i];
    if (tid < 64) b1s[tid] = b1[tid];
    __syncthreads();

    int warp = tid >> 5, lane = tid & 31;
    int node = blockIdx.x * 4 + warp;
    if (node >= N_NODES) return;

    fs[warp][lane]      = feat[node * 64 + lane];
    fs[warp][32 + lane] = feat[node * 64 + 32 + lane];
    __syncwarp();

    float aa = b1s[lane], aa2 = b1s[32 + lane];
    float ab = 0.0f,      ab2 = 0.0f;
#pragma unroll
    for (int k = 0; k < 64; k++) {
        float f = fs[warp][k];
        aa  = fmaf(f, W1s[k * 64 + lane],            aa);
        aa2 = fmaf(f, W1s[k * 64 + 32 + lane],       aa2);
        ab  = fmaf(f, W1s[(64 + k) * 64 + lane],      ab);
        ab2 = fmaf(f, W1s[(64 + k) * 64 + 32 + lane], ab2);
    }
    g_Pa[node * 64 + lane]      = aa;
    g_Pa[node * 64 + 32 + lane] = aa2;
    g_Pb[node * 64 + lane]      = ab;
    g_Pb[node * 64 + 32 + lane] = ab2;
}

// ---------------------------------------------------------------------------
// Edge kernel: one thread per edge.
// ---------------------------------------------------------------------------
__global__ __launch_bounds__(256) void edge_kernel(
    const void* __restrict__ ei_raw,        // [2, E] int32 or int64
    const float* __restrict__ W2,           // [64,32]
    const float* __restrict__ b2,           // [32]
    const float* __restrict__ W3,           // [32,1]
    const float* __restrict__ b3,           // [1]
    float* __restrict__ scores)
{
    __shared__ float W2s[64 * 32];
    __shared__ float W3s[32];
    __shared__ float b2s[32];
    __shared__ float b3s;
    __shared__ float red_v[8];
    __shared__ unsigned red_c[8];

    int tid = threadIdx.x;
    for (int i = tid; i < 64 * 32; i += 256) W2s[i] = W2[i];
    if (tid < 32) { W3s[tid] = W3[tid]; b2s[tid] = b2[tid]; }
    if (tid == 0) b3s = b3[0];
    __syncthreads();

    int e = blockIdx.x * 256 + tid;
    float score = 0.0f;
    bool valid = (e < N_EDGES);

    if (valid) {
        int s, t;
        if (g_idx64) {
            const long long* ei = (const long long*)ei_raw;
            s = (int)ei[e];
            t = (int)ei[N_EDGES + e];
        } else {
            const int* ei = (const int*)ei_raw;
            s = ei[e];
            t = ei[N_EDGES + e];
        }
        // defensive clamp (no-op when dtype detection is correct)
        s = min(max(s, 0), N_NODES - 1);
        t = min(max(t, 0), N_NODES - 1);

        const float4* pa = (const float4*)(g_Pa + (size_t)s * 64);
        const float4* pb = (const float4*)(g_Pb + (size_t)t * 64);

        float h1[64];
#pragma unroll
        for (int i = 0; i < 16; i++) {
            float4 a = pa[i];
            float4 b = pb[i];
            h1[4 * i + 0] = fmaxf(a.x + b.x, 0.0f);
            h1[4 * i + 1] = fmaxf(a.y + b.y, 0.0f);
            h1[4 * i + 2] = fmaxf(a.z + b.z, 0.0f);
            h1[4 * i + 3] = fmaxf(a.w + b.w, 0.0f);
        }

        float acc[32];
#pragma unroll
        for (int j = 0; j < 32; j++) acc[j] = b2s[j];

#pragma unroll
        for (int k = 0; k < 64; k++) {
            float h = h1[k];
            const float4* wrow = (const float4*)(W2s + k * 32);
#pragma unroll
            for (int j4 = 0; j4 < 8; j4++) {
                float4 w = wrow[j4];     // broadcast across warp
                acc[4 * j4 + 0] = fmaf(h, w.x, acc[4 * j4 + 0]);
                acc[4 * j4 + 1] = fmaf(h, w.y, acc[4 * j4 + 1]);
                acc[4 * j4 + 2] = fmaf(h, w.z, acc[4 * j4 + 2]);
                acc[4 * j4 + 3] = fmaf(h, w.w, acc[4 * j4 + 3]);
            }
        }

        float z = b3s;
#pragma unroll
        for (int j = 0; j < 32; j++)
            z = fmaf(fmaxf(acc[j], 0.0f), W3s[j], z);

        score = 1.0f / (1.0f + expf(-z));
        scores[e] = score;

        if (score < 0.7f) {
            float coeff = 0.05f * (1.0f - score);
            atomicAdd(&g_C[s], coeff);
            atomicAdd(&g_C[t], coeff);
        }
    }

    // block reduction of score sum + violation count
    float v = valid ? score : 0.0f;
    unsigned c = (valid && score < 0.7f) ? 1u : 0u;
#pragma unroll
    for (int o = 16; o > 0; o >>= 1) {
        v += __shfl_down_sync(0xFFFFFFFFu, v, o);
        c += __shfl_down_sync(0xFFFFFFFFu, c, o);
    }
    if ((tid & 31) == 0) { red_v[tid >> 5] = v; red_c[tid >> 5] = c; }
    __syncthreads();
    if (tid < 8) {
        v = red_v[tid];
        c = red_c[tid];
#pragma unroll
        for (int o = 4; o > 0; o >>= 1) {
            v += __shfl_down_sync(0xFFu, v, o);
            c += __shfl_down_sync(0xFFu, c, o);
        }
        if (tid == 0) {
            atomicAdd(&g_sum, v);
            atomicAdd(&g_cnt, c);
        }
    }
}

// ---------------------------------------------------------------------------
// Finalize: updated[n][f] = feat[n][f] + C[n] * tanh(feat[n][f])
// ---------------------------------------------------------------------------
__global__ __launch_bounds__(256) void finalize_kernel(
    const float* __restrict__ feat,
    float* __restrict__ out)
{
    int i = blockIdx.x * 256 + threadIdx.x;
    if (i < N_NODES * F_DIM) {
        float f = feat[i];
        float c = g_C[i >> 6];
        out[i] = fmaf(c, tanhf(f), f);
    }
    if (i == 0) {
        out[(size_t)N_NODES * F_DIM + N_EDGES]     = g_sum * (1.0f / (float)N_EDGES);
        out[(size_t)N_NODES * F_DIM + N_EDGES + 1] = (float)g_cnt;
    }
}

// ---------------------------------------------------------------------------
extern "C" void kernel_launch(void* const* d_in, const int* in_sizes, int n_in,
                              void* d_out, int out_size)
{
    const float* feat = (const float*)d_in[0];
    const void*  ei   = d_in[1];
    // d_in[2] = node_positions (unused), d_in[3] = node_radii (unused)
    const float* W1 = (const float*)d_in[4];
    const float* b1 = (const float*)d_in[5];
    const float* W2 = (const float*)d_in[6];
    const float* b2 = (const float*)d_in[7];
    const float* W3 = (const float*)d_in[8];
    const float* b3 = (const float*)d_in[9];

    float* out    = (float*)d_out;
    float* scores = out + (size_t)N_NODES * F_DIM;

    detect_kernel<<<1, 32>>>((const int*)ei);
    zero_kernel<<<(N_NODES + 255) / 256, 256>>>();
    precompute_kernel<<<(N_NODES + 3) / 4, 128>>>(feat, W1, b1);
    edge_kernel<<<(N_EDGES + 255) / 256, 256>>>(ei, W2, b2, W3, b3, scores);
    finalize_kernel<<<(N_NODES * F_DIM + 255) / 256, 256>>>(feat, out);
}